// round 2
// baseline (speedup 1.0000x reference)
#include <cuda_runtime.h>
#include <math.h>

// ---------------- model constants ----------------
#define TT   2048      // total tokens B*S
#define DD   2048      // hidden
#define HH   16        // heads
#define HDIM 128       // head dim
#define SS   1024      // seq len
#define BBATCH 2
#define FFN  8192
#define QKN  2304      // D + 2*HD
#define NLAYER 2
#define LN_EPS 1e-5f
#define ATT_SCALE 0.08838834764831845f  // HD^-0.5

// ---------------- scratch (device globals, no allocs) ----------------
__device__ float g_h   [TT * DD];
__device__ float g_res [TT * DD];
__device__ float g_res2[TT * DD];
__device__ float g_x   [TT * DD];
__device__ float g_qkv [TT * QKN];
__device__ float g_ctx [TT * DD];
__device__ float g_attn[TT * DD];
__device__ float g_ff  [TT * FFN];

// ---------------- embed: h = wte[ids] + wpe[pos] ----------------
__global__ void embed_kernel(const int* __restrict__ ids,
                             const int* __restrict__ pos,
                             const float* __restrict__ wte,
                             const float* __restrict__ wpe,
                             float* __restrict__ out)
{
    int idx = blockIdx.x * blockDim.x + threadIdx.x;
    if (idx >= TT * DD) return;
    int t = idx >> 11;       // /DD
    int d = idx & (DD - 1);
    out[idx] = wte[(size_t)ids[t] * DD + d] + wpe[(size_t)pos[t] * DD + d];
}

// ---------------- fused residual-add + LayerNorm ----------------
// res = a + (r ? r : 0); res_out = res (optional); x_out = LN(res)*g + b
__global__ __launch_bounds__(256)
void ln_kernel(const float* __restrict__ a, const float* __restrict__ r,
               const float* __restrict__ g, const float* __restrict__ b,
               float* __restrict__ res_out, float* __restrict__ x_out)
{
    const int t = blockIdx.x;
    const size_t base = (size_t)t * DD;
    float v[8];
    float s = 0.f, sq = 0.f;
#pragma unroll
    for (int i = 0; i < 8; i++) {
        int idx = threadIdx.x + i * 256;
        float val = a[base + idx];
        if (r) val += r[base + idx];
        v[i] = val; s += val; sq += val * val;
    }
    int lane = threadIdx.x & 31, wid = threadIdx.x >> 5;
#pragma unroll
    for (int o = 16; o; o >>= 1) {
        s  += __shfl_xor_sync(0xffffffffu, s,  o);
        sq += __shfl_xor_sync(0xffffffffu, sq, o);
    }
    __shared__ float shs[8], shq[8];
    __shared__ float smean, srstd;
    if (lane == 0) { shs[wid] = s; shq[wid] = sq; }
    __syncthreads();
    if (threadIdx.x == 0) {
        float ts = 0.f, tq = 0.f;
#pragma unroll
        for (int i = 0; i < 8; i++) { ts += shs[i]; tq += shq[i]; }
        float mean = ts * (1.f / DD);
        float var  = tq * (1.f / DD) - mean * mean;
        smean = mean;
        srstd = rsqrtf(var + LN_EPS);
    }
    __syncthreads();
    float mean = smean, rstd = srstd;
#pragma unroll
    for (int i = 0; i < 8; i++) {
        int idx = threadIdx.x + i * 256;
        if (res_out) res_out[base + idx] = v[i];
        x_out[base + idx] = (v[i] - mean) * rstd * g[idx] + b[idx];
    }
}

// ---------------- SGEMM: C[M,N] = A[M,K] @ B[K,N] + bias (+gelu) ----------------
// M,N multiple of 128; K multiple of 8. 128x128 tile, 8x8/thread, double-buffered.
__device__ __forceinline__ float gelu_tanh(float x) {
    float x3 = x * x * x;
    float t = tanhf(0.7978845608028654f * (x + 0.044715f * x3));
    return 0.5f * x * (1.f + t);
}

__global__ __launch_bounds__(256)
void sgemm_kernel(const float* __restrict__ A, const float* __restrict__ B,
                  const float* __restrict__ bias, float* __restrict__ C,
                  int M, int N, int K, int act)
{
    __shared__ float As[2][8][128];
    __shared__ float Bs[2][8][128];

    const int tid = threadIdx.x;
    const int bm = blockIdx.y * 128;
    const int bn = blockIdx.x * 128;

    const int arow = tid >> 1;          // 0..127
    const int acol = (tid & 1) << 2;    // 0 or 4
    const int brow = tid >> 5;          // 0..7
    const int bcol = (tid & 31) << 2;   // 0..124

    const int ty = (tid >> 4) << 3;     // row tile 0..120
    const int tx = (tid & 15) << 3;     // col tile 0..120

    const float* Ag = A + (size_t)(bm + arow) * K + acol;
    const float* Bg = B + (size_t)brow * N + bn + bcol;

    // prologue: tile 0
    {
        float4 av = *(const float4*)Ag;
        float4 bv = *(const float4*)Bg;
        As[0][acol + 0][arow] = av.x;
        As[0][acol + 1][arow] = av.y;
        As[0][acol + 2][arow] = av.z;
        As[0][acol + 3][arow] = av.w;
        *(float4*)&Bs[0][brow][bcol] = bv;
    }
    __syncthreads();

    float acc[8][8] = {};
    int buf = 0;
    const int nk = K >> 3;

#define MMA_TILE(BUF)                                                        \
    {                                                                        \
        _Pragma("unroll")                                                    \
        for (int kk = 0; kk < 8; kk++) {                                     \
            float ar[8], br[8];                                              \
            _Pragma("unroll")                                                \
            for (int i = 0; i < 8; i++) ar[i] = As[BUF][kk][ty + i];         \
            _Pragma("unroll")                                                \
            for (int j = 0; j < 8; j++) br[j] = Bs[BUF][kk][tx + j];         \
            _Pragma("unroll")                                                \
            for (int i = 0; i < 8; i++)                                      \
                _Pragma("unroll")                                            \
                for (int j = 0; j < 8; j++)                                  \
                    acc[i][j] += ar[i] * br[j];                              \
        }                                                                    \
    }

    for (int it = 1; it < nk; it++) {
        const int k0 = it << 3;
        float4 av = *(const float4*)(Ag + k0);
        float4 bv = *(const float4*)(Bg + (size_t)k0 * N);
        MMA_TILE(buf);
        buf ^= 1;
        As[buf][acol + 0][arow] = av.x;
        As[buf][acol + 1][arow] = av.y;
        As[buf][acol + 2][arow] = av.z;
        As[buf][acol + 3][arow] = av.w;
        *(float4*)&Bs[buf][brow][bcol] = bv;
        __syncthreads();
    }
    MMA_TILE(buf);
#undef MMA_TILE

    // epilogue: bias (+gelu), vectorized stores
#pragma unroll
    for (int i = 0; i < 8; i++) {
        const size_t row = (size_t)(bm + ty + i) * N;
#pragma unroll
        for (int j = 0; j < 8; j += 4) {
            int col = bn + tx + j;
            float4 v;
            v.x = acc[i][j + 0] + bias[col + 0];
            v.y = acc[i][j + 1] + bias[col + 1];
            v.z = acc[i][j + 2] + bias[col + 2];
            v.w = acc[i][j + 3] + bias[col + 3];
            if (act) {
                v.x = gelu_tanh(v.x); v.y = gelu_tanh(v.y);
                v.z = gelu_tanh(v.z); v.w = gelu_tanh(v.w);
            }
            *(float4*)(C + row + col) = v;
        }
    }
}

// ---------------- MQA causal attention (online softmax, one warp per q-row/head) ----------------
__global__ __launch_bounds__(256)
void attn_kernel(const float* __restrict__ qkv, float* __restrict__ ctx)
{
    const int gwarp = (blockIdx.x * blockDim.x + threadIdx.x) >> 5;
    const int lane  = threadIdx.x & 31;
    if (gwarp >= BBATCH * HH * SS) return;

    const int s = gwarp & (SS - 1);
    const int h = (gwarp >> 10) & (HH - 1);
    const int b = gwarp >> 14;
    const int t = b * SS + s;

    const float4 q = *(const float4*)(qkv + (size_t)t * QKN + h * HDIM + lane * 4);
    const float* kb = qkv + (size_t)(b * SS) * QKN + DD;        // k at col D
    // v at col D + HDIM = kb + HDIM

    float m = -1e30f, l = 0.f;
    float4 acc = make_float4(0.f, 0.f, 0.f, 0.f);

    for (int j = 0; j <= s; j++) {
        const float* kp = kb + (size_t)j * QKN;
        float4 kv = *(const float4*)(kp + lane * 4);
        float p = q.x * kv.x + q.y * kv.y + q.z * kv.z + q.w * kv.w;
#pragma unroll
        for (int o = 16; o; o >>= 1) p += __shfl_xor_sync(0xffffffffu, p, o);
        p *= ATT_SCALE;
        float nm = fmaxf(m, p);
        float f  = __expf(m - nm);
        float e  = __expf(p - nm);
        m = nm;
        l = l * f + e;
        float4 vv = *(const float4*)(kp + HDIM + lane * 4);
        acc.x = acc.x * f + e * vv.x;
        acc.y = acc.y * f + e * vv.y;
        acc.z = acc.z * f + e * vv.z;
        acc.w = acc.w * f + e * vv.w;
    }
    float inv = 1.f / l;
    float4 o4 = make_float4(acc.x * inv, acc.y * inv, acc.z * inv, acc.w * inv);
    *(float4*)(ctx + (size_t)t * DD + h * HDIM + lane * 4) = o4;
}

// ---------------- launch ----------------
extern "C" void kernel_launch(void* const* d_in, const int* in_sizes, int n_in,
                              void* d_out, int out_size)
{
    const int*   ids      = (const int*)  d_in[0];
    const int*   pos      = (const int*)  d_in[1];
    const float* wte      = (const float*)d_in[2];
    const float* wpe      = (const float*)d_in[3];
    const float* c_attn_w = (const float*)d_in[4];
    const float* c_attn_b = (const float*)d_in[5];
    const float* c_proj_w = (const float*)d_in[6];
    const float* c_proj_b = (const float*)d_in[7];
    const float* ln1_w    = (const float*)d_in[8];
    const float* ln1_b    = (const float*)d_in[9];
    const float* ln2_w    = (const float*)d_in[10];
    const float* ln2_b    = (const float*)d_in[11];
    const float* fc_w     = (const float*)d_in[12];
    const float* fc_b     = (const float*)d_in[13];
    const float* mp_w     = (const float*)d_in[14];
    const float* mp_b     = (const float*)d_in[15];
    const float* lnf_w    = (const float*)d_in[16];
    const float* lnf_b    = (const float*)d_in[17];
    float* out = (float*)d_out;

    float *h, *res, *res2, *x, *qkv, *ctx, *attn, *ff;
    cudaGetSymbolAddress((void**)&h,    g_h);
    cudaGetSymbolAddress((void**)&res,  g_res);
    cudaGetSymbolAddress((void**)&res2, g_res2);
    cudaGetSymbolAddress((void**)&x,    g_x);
    cudaGetSymbolAddress((void**)&qkv,  g_qkv);
    cudaGetSymbolAddress((void**)&ctx,  g_ctx);
    cudaGetSymbolAddress((void**)&attn, g_attn);
    cudaGetSymbolAddress((void**)&ff,   g_ff);

    // embed
    embed_kernel<<<(TT * DD + 255) / 256, 256>>>(ids, pos, wte, wpe, h);

    const dim3 blk(256);
    for (int l = 0; l < NLAYER; l++) {
        const float* law = c_attn_w + (size_t)l * DD * QKN;
        const float* lab = c_attn_b + (size_t)l * QKN;
        const float* lpw = c_proj_w + (size_t)l * DD * DD;
        const float* lpb = c_proj_b + (size_t)l * DD;
        const float* lfw = fc_w     + (size_t)l * DD * FFN;
        const float* lfb = fc_b     + (size_t)l * FFN;
        const float* lmw = mp_w     + (size_t)l * FFN * DD;
        const float* lmb = mp_b     + (size_t)l * DD;

        // ln1: res = h (+ residual), x = LN(res)
        ln_kernel<<<TT, blk>>>(h, (l == 0) ? nullptr : res2,
                               ln1_w + (size_t)l * DD, ln1_b + (size_t)l * DD,
                               res, x);

        // qkv = x @ c_attn_w + b
        sgemm_kernel<<<dim3(QKN / 128, TT / 128), blk>>>(x, law, lab, qkv, TT, QKN, DD, 0);

        // attention -> ctx
        attn_kernel<<<(BBATCH * HH * SS * 32 + 255) / 256, blk>>>(qkv, ctx);

        // attn = ctx @ c_proj_w + b
        sgemm_kernel<<<dim3(DD / 128, TT / 128), blk>>>(ctx, lpw, lpb, attn, TT, DD, DD, 0);

        // ln2: res2 = attn + res, x = LN(res2)
        ln_kernel<<<TT, blk>>>(attn, res,
                               ln2_w + (size_t)l * DD, ln2_b + (size_t)l * DD,
                               res2, x);

        // ff = gelu(x @ fc_w + b)
        sgemm_kernel<<<dim3(FFN / 128, TT / 128), blk>>>(x, lfw, lfb, ff, TT, FFN, DD, 1);

        // h = ff @ mp_w + b
        sgemm_kernel<<<dim3(DD / 128, TT / 128), blk>>>(ff, lmw, lmb, h, TT, DD, FFN, 0);
    }

    // final: out = LN(h + res2)
    ln_kernel<<<TT, blk>>>(h, res2, lnf_w, lnf_b, nullptr, out);
}

// round 4
// speedup vs baseline: 1.9375x; 1.9375x over previous
#include <cuda_runtime.h>
#include <cuda_bf16.h>
#include <math.h>
#include <stdint.h>

// ---------------- model constants ----------------
#define TT   2048
#define DD   2048
#define HH   16
#define HDIM 128
#define SS   1024
#define BB   2
#define FFN  8192
#define QKN  2304
#define NL   2
#define LN_EPS 1e-5f
#define ATT_SCALE 0.08838834764831845f

// ---------------- fp32 scratch ----------------
__device__ float g_h   [TT * DD];
__device__ float g_res [TT * DD];
__device__ float g_res2[TT * DD];
__device__ float g_qkv [TT * QKN];
__device__ float g_attn[TT * DD];

// ---------------- bf16 hi/lo activation splits ----------------
__device__ __align__(16) __nv_bfloat16 g_xh[TT*DD],  g_xl[TT*DD];
__device__ __align__(16) __nv_bfloat16 g_ch[TT*DD],  g_cl[TT*DD];
__device__ __align__(16) __nv_bfloat16 g_fh[TT*FFN], g_fl[TT*FFN];

// transposed weights [N][K], hi/lo
__device__ __align__(16) __nv_bfloat16 g_wqh[NL*QKN*DD], g_wql[NL*QKN*DD];
__device__ __align__(16) __nv_bfloat16 g_wph[NL*DD*DD],  g_wpl[NL*DD*DD];
__device__ __align__(16) __nv_bfloat16 g_wfh[NL*FFN*DD], g_wfl[NL*FFN*DD];
__device__ __align__(16) __nv_bfloat16 g_wmh[NL*DD*FFN], g_wml[NL*DD*FFN];

// ---------------- PTX helpers (all plain sm_80/sm_90 — no 'a' features) ----------------
__device__ __forceinline__ uint32_t s2u(const void* p) {
    uint32_t a;
    asm("{ .reg .u64 t; cvta.to.shared.u64 t, %1; cvt.u32.u64 %0, t; }" : "=r"(a) : "l"(p));
    return a;
}
__device__ __forceinline__ uint32_t sw128(uint32_t o) { return o ^ ((o >> 3) & 0x70); }
__device__ __forceinline__ void cp16(uint32_t d, const void* s) {
    asm volatile("cp.async.cg.shared.global [%0], [%1], 16;" :: "r"(d), "l"(s));
}
#define CP_COMMIT() asm volatile("cp.async.commit_group;" ::: "memory")
#define CP_WAIT1()  asm volatile("cp.async.wait_group 1;" ::: "memory")
#define CP_WAIT0()  asm volatile("cp.async.wait_group 0;" ::: "memory")

#define LDSM4(R0, R1, R2, R3, ADDR) \
    asm volatile("ldmatrix.sync.aligned.m8n8.x4.shared.b16 {%0,%1,%2,%3}, [%4];" \
        : "=r"(R0), "=r"(R1), "=r"(R2), "=r"(R3) : "r"(ADDR))

#define MMA16816(D, A, B0, B1) \
    asm volatile("mma.sync.aligned.m16n8k16.row.col.f32.bf16.bf16.f32 " \
        "{%0,%1,%2,%3}, {%4,%5,%6,%7}, {%8,%9}, {%0,%1,%2,%3};" \
        : "+f"((D)[0]), "+f"((D)[1]), "+f"((D)[2]), "+f"((D)[3]) \
        : "r"((A)[0]), "r"((A)[1]), "r"((A)[2]), "r"((A)[3]), "r"(B0), "r"(B1))

// ---------------- embed ----------------
__global__ void embed_kernel(const int* __restrict__ ids, const int* __restrict__ pos,
                             const float* __restrict__ wte, const float* __restrict__ wpe,
                             float* __restrict__ out)
{
    int idx = blockIdx.x * blockDim.x + threadIdx.x;
    if (idx >= TT * DD) return;
    int t = idx >> 11, d = idx & (DD - 1);
    out[idx] = wte[(size_t)ids[t] * DD + d] + wpe[(size_t)pos[t] * DD + d];
}

// ---------------- fused residual-add + LayerNorm (+ bf16 hi/lo split out) ----------------
__global__ __launch_bounds__(256)
void ln_kernel(const float* __restrict__ a, const float* __restrict__ r,
               const float* __restrict__ g, const float* __restrict__ b,
               float* __restrict__ res_out, float* __restrict__ xf,
               __nv_bfloat16* __restrict__ xh, __nv_bfloat16* __restrict__ xl)
{
    const int t = blockIdx.x;
    const size_t base = (size_t)t * DD;
    float v[8];
    float s = 0.f, sq = 0.f;
#pragma unroll
    for (int i = 0; i < 8; i++) {
        int idx = threadIdx.x + i * 256;
        float val = a[base + idx];
        if (r) val += r[base + idx];
        v[i] = val; s += val; sq += val * val;
    }
    int lane = threadIdx.x & 31, wid = threadIdx.x >> 5;
#pragma unroll
    for (int o = 16; o; o >>= 1) {
        s  += __shfl_xor_sync(0xffffffffu, s,  o);
        sq += __shfl_xor_sync(0xffffffffu, sq, o);
    }
    __shared__ float shs[8], shq[8], smean, srstd;
    if (lane == 0) { shs[wid] = s; shq[wid] = sq; }
    __syncthreads();
    if (threadIdx.x == 0) {
        float ts = 0.f, tq = 0.f;
#pragma unroll
        for (int i = 0; i < 8; i++) { ts += shs[i]; tq += shq[i]; }
        float mean = ts * (1.f / DD);
        float var  = tq * (1.f / DD) - mean * mean;
        smean = mean; srstd = rsqrtf(var + LN_EPS);
    }
    __syncthreads();
    float mean = smean, rstd = srstd;
#pragma unroll
    for (int i = 0; i < 8; i++) {
        int idx = threadIdx.x + i * 256;
        if (res_out) res_out[base + idx] = v[i];
        float y = (v[i] - mean) * rstd * g[idx] + b[idx];
        if (xf) xf[base + idx] = y;
        if (xh) {
            __nv_bfloat16 hh = __float2bfloat16(y);
            xh[base + idx] = hh;
            xl[base + idx] = __float2bfloat16(y - __bfloat162float(hh));
        }
    }
}

// ---------------- weight transpose + bf16 split: W[K][N] -> T{h,l}[N][K] ----------------
__global__ __launch_bounds__(256)
void tsplit_kernel(const float* __restrict__ W, __nv_bfloat16* __restrict__ Th,
                   __nv_bfloat16* __restrict__ Tl, int K, int N)
{
    __shared__ float t[32][33];
    int k0 = blockIdx.y * 32, n0 = blockIdx.x * 32;
    int tx = threadIdx.x & 31, ty = threadIdx.x >> 5;
#pragma unroll
    for (int i = 0; i < 4; i++)
        t[ty + i * 8][tx] = W[(size_t)(k0 + ty + i * 8) * N + n0 + tx];
    __syncthreads();
#pragma unroll
    for (int i = 0; i < 4; i++) {
        int n = ty + i * 8;
        float v = t[tx][n];
        __nv_bfloat16 h = __float2bfloat16(v);
        size_t o = (size_t)(n0 + n) * K + k0 + tx;
        Th[o] = h;
        Tl[o] = __float2bfloat16(v - __bfloat162float(h));
    }
}

// ---------------- bf16x3 warp-MMA GEMM ----------------
// C[M,N] = A[M,K] @ B[N,K]^T + bias. CTA 128x128, K-chunk 64, 8 warps (2x4),
// warp tile 64x32. SMEM per buf: Ah|Al|Bh|Bl = 4 x 16KB; double buffered = 128KB.
#define SMEM_GEMM 131072

__device__ __forceinline__ void load_tiles(
    const __nv_bfloat16* Ah, const __nv_bfloat16* Al,
    const __nv_bfloat16* Bh, const __nv_bfloat16* Bl,
    uint32_t base, int bm, int bn, int k0, int K, int tid)
{
#pragma unroll
    for (int i = 0; i < 8; i++) {
        int idx = tid + i * 256;           // split(1)|row(7)|seg(3)
        int s = idx >> 10, row = (idx >> 3) & 127, seg = idx & 7;
        const __nv_bfloat16* src = (s ? Al : Ah) + (size_t)(bm + row) * K + k0 + seg * 8;
        cp16(base + s * 16384 + sw128(row * 128 + seg * 16), src);
    }
#pragma unroll
    for (int i = 0; i < 8; i++) {
        int idx = tid + i * 256;
        int s = idx >> 10, row = (idx >> 3) & 127, seg = idx & 7;
        const __nv_bfloat16* src = (s ? Bl : Bh) + (size_t)(bn + row) * K + k0 + seg * 8;
        cp16(base + 32768 + s * 16384 + sw128(row * 128 + seg * 16), src);
    }
}

__device__ __forceinline__ float gelu_tanh(float x) {
    float x3 = x * x * x;
    float t = tanhf(0.7978845608028654f * (x + 0.044715f * x3));
    return 0.5f * x * (1.f + t);
}

__global__ __launch_bounds__(256)
void gemm_kernel(const __nv_bfloat16* __restrict__ Ah, const __nv_bfloat16* __restrict__ Al,
                 const __nv_bfloat16* __restrict__ Bh, const __nv_bfloat16* __restrict__ Bl,
                 const float* __restrict__ bias, float* __restrict__ Cf,
                 __nv_bfloat16* __restrict__ Ch, __nv_bfloat16* __restrict__ Cl,
                 int M, int N, int K, int act)
{
    extern __shared__ char smem[];
    const uint32_t sb = s2u(smem);
    const int tid = threadIdx.x;
    const int bm = blockIdx.y * 128, bn = blockIdx.x * 128;
    const int lane = tid & 31, wid = tid >> 5;
    const int wm = wid >> 2, wn = wid & 3;

    // ldmatrix lane address components: row = lane%16, 16B col set = lane/16
    const int lrow = lane & 15;
    const uint32_t lcol = (uint32_t)(lane >> 4) * 16;
    uint32_t aOff[4], bOff[2];
#pragma unroll
    for (int mf = 0; mf < 4; mf++)
        aOff[mf] = (uint32_t)(wm * 64 + mf * 16 + lrow) * 128 + lcol;
#pragma unroll
    for (int np = 0; np < 2; np++)
        bOff[np] = (uint32_t)(wn * 32 + np * 16 + lrow) * 128 + lcol;

    float acc[4][4][4];
#pragma unroll
    for (int i = 0; i < 4; i++)
#pragma unroll
        for (int j = 0; j < 4; j++)
#pragma unroll
            for (int c = 0; c < 4; c++) acc[i][j][c] = 0.f;

    const int nk = K >> 6;
    load_tiles(Ah, Al, Bh, Bl, sb,         bm, bn, 0,  K, tid); CP_COMMIT();
    load_tiles(Ah, Al, Bh, Bl, sb + 65536, bm, bn, 64, K, tid); CP_COMMIT();

    for (int it = 0; it < nk; it++) {
        const int b = it & 1;
        if (it + 2 <= nk) { CP_WAIT1(); } else { CP_WAIT0(); }
        __syncthreads();

        const uint32_t ahS = sb + (uint32_t)b * 65536;
        const uint32_t alS = ahS + 16384;
        const uint32_t bhS = ahS + 32768;
        const uint32_t blS = ahS + 49152;

#pragma unroll
        for (int ks = 0; ks < 4; ks++) {
            const uint32_t ko = (uint32_t)ks * 32;
            uint32_t ah[4][4], al[4][4], bh[2][4], bl[2][4];
#pragma unroll
            for (int mf = 0; mf < 4; mf++)
                LDSM4(ah[mf][0], ah[mf][1], ah[mf][2], ah[mf][3], ahS + sw128(aOff[mf] + ko));
#pragma unroll
            for (int np = 0; np < 2; np++)
                LDSM4(bh[np][0], bh[np][1], bh[np][2], bh[np][3], bhS + sw128(bOff[np] + ko));
#pragma unroll
            for (int mf = 0; mf < 4; mf++)
#pragma unroll
                for (int nf = 0; nf < 4; nf++)
                    MMA16816(acc[mf][nf], ah[mf], bh[nf >> 1][nf & 1], bh[nf >> 1][(nf & 1) + 2]);
#pragma unroll
            for (int np = 0; np < 2; np++)
                LDSM4(bl[np][0], bl[np][1], bl[np][2], bl[np][3], blS + sw128(bOff[np] + ko));
#pragma unroll
            for (int mf = 0; mf < 4; mf++)
#pragma unroll
                for (int nf = 0; nf < 4; nf++)
                    MMA16816(acc[mf][nf], ah[mf], bl[nf >> 1][nf & 1], bl[nf >> 1][(nf & 1) + 2]);
#pragma unroll
            for (int mf = 0; mf < 4; mf++)
                LDSM4(al[mf][0], al[mf][1], al[mf][2], al[mf][3], alS + sw128(aOff[mf] + ko));
#pragma unroll
            for (int mf = 0; mf < 4; mf++)
#pragma unroll
                for (int nf = 0; nf < 4; nf++)
                    MMA16816(acc[mf][nf], al[mf], bh[nf >> 1][nf & 1], bh[nf >> 1][(nf & 1) + 2]);
        }
        __syncthreads();
        if (it + 2 < nk) {
            load_tiles(Ah, Al, Bh, Bl, sb + (uint32_t)b * 65536, bm, bn, (it + 2) * 64, K, tid);
            CP_COMMIT();
        }
    }

    // epilogue: C frag (g, tg*2) mapping — direct register -> global
    const int g = lane >> 2, tg = lane & 3;
#pragma unroll
    for (int mf = 0; mf < 4; mf++) {
#pragma unroll
        for (int nf = 0; nf < 4; nf++) {
            const int col = bn + wn * 32 + nf * 8 + tg * 2;
            const float bx = bias[col], by = bias[col + 1];
#pragma unroll
            for (int half = 0; half < 2; half++) {
                const int row = bm + wm * 64 + mf * 16 + g + half * 8;
                float vx = acc[mf][nf][half * 2 + 0] + bx;
                float vy = acc[mf][nf][half * 2 + 1] + by;
                if (act) { vx = gelu_tanh(vx); vy = gelu_tanh(vy); }
                const size_t o = (size_t)row * N + col;
                if (Cf) { float2 f2 = make_float2(vx, vy); *(float2*)(Cf + o) = f2; }
                if (Ch) {
                    __nv_bfloat16 h0 = __float2bfloat16(vx), h1 = __float2bfloat16(vy);
                    __nv_bfloat162 p; p.x = h0; p.y = h1;
                    *(__nv_bfloat162*)(Ch + o) = p;
                    __nv_bfloat162 q;
                    q.x = __float2bfloat16(vx - __bfloat162float(h0));
                    q.y = __float2bfloat16(vy - __bfloat162float(h1));
                    *(__nv_bfloat162*)(Cl + o) = q;
                }
            }
        }
    }
}

// ---------------- MQA causal attention (writes ctx as bf16 hi/lo) ----------------
__global__ __launch_bounds__(256)
void attn_kernel(const float* __restrict__ qkv,
                 __nv_bfloat16* __restrict__ ch, __nv_bfloat16* __restrict__ cl)
{
    const int gwarp = (blockIdx.x * blockDim.x + threadIdx.x) >> 5;
    const int lane  = threadIdx.x & 31;
    if (gwarp >= BB * HH * SS) return;

    const int s = gwarp & (SS - 1);
    const int h = (gwarp >> 10) & (HH - 1);
    const int b = gwarp >> 14;
    const int t = b * SS + s;

    const float4 q = *(const float4*)(qkv + (size_t)t * QKN + h * HDIM + lane * 4);
    const float* kb = qkv + (size_t)(b * SS) * QKN + DD;

    float m = -1e30f, l = 0.f;
    float4 acc = make_float4(0.f, 0.f, 0.f, 0.f);

    for (int j = 0; j <= s; j++) {
        const float* kp = kb + (size_t)j * QKN;
        float4 kv = *(const float4*)(kp + lane * 4);
        float p = q.x * kv.x + q.y * kv.y + q.z * kv.z + q.w * kv.w;
#pragma unroll
        for (int o = 16; o; o >>= 1) p += __shfl_xor_sync(0xffffffffu, p, o);
        p *= ATT_SCALE;
        float nm = fmaxf(m, p);
        float f = __expf(m - nm), e = __expf(p - nm);
        m = nm; l = l * f + e;
        float4 vv = *(const float4*)(kp + HDIM + lane * 4);
        acc.x = acc.x * f + e * vv.x;
        acc.y = acc.y * f + e * vv.y;
        acc.z = acc.z * f + e * vv.z;
        acc.w = acc.w * f + e * vv.w;
    }
    float inv = 1.f / l;
    float4 o4 = make_float4(acc.x * inv, acc.y * inv, acc.z * inv, acc.w * inv);
    size_t off = (size_t)t * DD + h * HDIM + lane * 4;
    __nv_bfloat16 h0 = __float2bfloat16(o4.x), h1 = __float2bfloat16(o4.y);
    __nv_bfloat16 h2 = __float2bfloat16(o4.z), h3 = __float2bfloat16(o4.w);
    __nv_bfloat162 p0; p0.x = h0; p0.y = h1;
    __nv_bfloat162 p1; p1.x = h2; p1.y = h3;
    *(__nv_bfloat162*)(ch + off)     = p0;
    *(__nv_bfloat162*)(ch + off + 2) = p1;
    __nv_bfloat162 q0, q1;
    q0.x = __float2bfloat16(o4.x - __bfloat162float(h0));
    q0.y = __float2bfloat16(o4.y - __bfloat162float(h1));
    q1.x = __float2bfloat16(o4.z - __bfloat162float(h2));
    q1.y = __float2bfloat16(o4.w - __bfloat162float(h3));
    *(__nv_bfloat162*)(cl + off)     = q0;
    *(__nv_bfloat162*)(cl + off + 2) = q1;
}

// ---------------- launch ----------------
extern "C" void kernel_launch(void* const* d_in, const int* in_sizes, int n_in,
                              void* d_out, int out_size)
{
    const int*   ids      = (const int*)  d_in[0];
    const int*   pos      = (const int*)  d_in[1];
    const float* wte      = (const float*)d_in[2];
    const float* wpe      = (const float*)d_in[3];
    const float* c_attn_w = (const float*)d_in[4];
    const float* c_attn_b = (const float*)d_in[5];
    const float* c_proj_w = (const float*)d_in[6];
    const float* c_proj_b = (const float*)d_in[7];
    const float* ln1_w    = (const float*)d_in[8];
    const float* ln1_b    = (const float*)d_in[9];
    const float* ln2_w    = (const float*)d_in[10];
    const float* ln2_b    = (const float*)d_in[11];
    const float* fc_w     = (const float*)d_in[12];
    const float* fc_b     = (const float*)d_in[13];
    const float* mp_w     = (const float*)d_in[14];
    const float* mp_b     = (const float*)d_in[15];
    const float* lnf_w    = (const float*)d_in[16];
    const float* lnf_b    = (const float*)d_in[17];
    float* out = (float*)d_out;

    float *h, *res, *res2, *qkv, *attn;
    __nv_bfloat16 *xh, *xl, *ch, *cl, *fh, *fl;
    __nv_bfloat16 *wqh, *wql, *wph, *wpl, *wfh, *wfl, *wmh, *wml;
    cudaGetSymbolAddress((void**)&h,    g_h);
    cudaGetSymbolAddress((void**)&res,  g_res);
    cudaGetSymbolAddress((void**)&res2, g_res2);
    cudaGetSymbolAddress((void**)&qkv,  g_qkv);
    cudaGetSymbolAddress((void**)&attn, g_attn);
    cudaGetSymbolAddress((void**)&xh,   g_xh);
    cudaGetSymbolAddress((void**)&xl,   g_xl);
    cudaGetSymbolAddress((void**)&ch,   g_ch);
    cudaGetSymbolAddress((void**)&cl,   g_cl);
    cudaGetSymbolAddress((void**)&fh,   g_fh);
    cudaGetSymbolAddress((void**)&fl,   g_fl);
    cudaGetSymbolAddress((void**)&wqh,  g_wqh);
    cudaGetSymbolAddress((void**)&wql,  g_wql);
    cudaGetSymbolAddress((void**)&wph,  g_wph);
    cudaGetSymbolAddress((void**)&wpl,  g_wpl);
    cudaGetSymbolAddress((void**)&wfh,  g_wfh);
    cudaGetSymbolAddress((void**)&wfl,  g_wfl);
    cudaGetSymbolAddress((void**)&wmh,  g_wmh);
    cudaGetSymbolAddress((void**)&wml,  g_wml);

    cudaFuncSetAttribute(gemm_kernel, cudaFuncAttributeMaxDynamicSharedMemorySize, SMEM_GEMM);

    // weight transposes + splits
    for (int l = 0; l < NL; l++) {
        tsplit_kernel<<<dim3(QKN / 32, DD / 32), 256>>>(
            c_attn_w + (size_t)l * DD * QKN, wqh + (size_t)l * QKN * DD, wql + (size_t)l * QKN * DD, DD, QKN);
        tsplit_kernel<<<dim3(DD / 32, DD / 32), 256>>>(
            c_proj_w + (size_t)l * DD * DD, wph + (size_t)l * DD * DD, wpl + (size_t)l * DD * DD, DD, DD);
        tsplit_kernel<<<dim3(FFN / 32, DD / 32), 256>>>(
            fc_w + (size_t)l * DD * FFN, wfh + (size_t)l * FFN * DD, wfl + (size_t)l * FFN * DD, DD, FFN);
        tsplit_kernel<<<dim3(DD / 32, FFN / 32), 256>>>(
            mp_w + (size_t)l * FFN * DD, wmh + (size_t)l * DD * FFN, wml + (size_t)l * DD * FFN, FFN, DD);
    }

    embed_kernel<<<(TT * DD + 255) / 256, 256>>>(ids, pos, wte, wpe, h);

    for (int l = 0; l < NL; l++) {
        ln_kernel<<<TT, 256>>>(h, (l == 0) ? nullptr : res2,
                               ln1_w + (size_t)l * DD, ln1_b + (size_t)l * DD,
                               res, nullptr, xh, xl);
        gemm_kernel<<<dim3(QKN / 128, TT / 128), 256, SMEM_GEMM>>>(
            xh, xl, wqh + (size_t)l * QKN * DD, wql + (size_t)l * QKN * DD,
            c_attn_b + (size_t)l * QKN, qkv, nullptr, nullptr, TT, QKN, DD, 0);
        attn_kernel<<<(BB * HH * SS * 32 + 255) / 256, 256>>>(qkv, ch, cl);
        gemm_kernel<<<dim3(DD / 128, TT / 128), 256, SMEM_GEMM>>>(
            ch, cl, wph + (size_t)l * DD * DD, wpl + (size_t)l * DD * DD,
            c_proj_b + (size_t)l * DD, attn, nullptr, nullptr, TT, DD, DD, 0);
        ln_kernel<<<TT, 256>>>(attn, res,
                               ln2_w + (size_t)l * DD, ln2_b + (size_t)l * DD,
                               res2, nullptr, xh, xl);
        gemm_kernel<<<dim3(FFN / 128, TT / 128), 256, SMEM_GEMM>>>(
            xh, xl, wfh + (size_t)l * FFN * DD, wfl + (size_t)l * FFN * DD,
            fc_b + (size_t)l * FFN, nullptr, fh, fl, TT, FFN, DD, 1);
        gemm_kernel<<<dim3(DD / 128, TT / 128), 256, SMEM_GEMM>>>(
            fh, fl, wmh + (size_t)l * DD * FFN, wml + (size_t)l * DD * FFN,
            mp_b + (size_t)l * DD, h, nullptr, nullptr, TT, DD, FFN, 0);
    }

    ln_kernel<<<TT, 256>>>(h, res2, lnf_w, lnf_b, nullptr, out, nullptr, nullptr);
}